// round 6
// baseline (speedup 1.0000x reference)
#include <cuda_runtime.h>
#include <math.h>

// Problem constants (fixed by the reference)
#define BB 4
#define TT 256
#define SS 16384
#define EE 256
#define HH 8
#define DD 32

// Scratch (allocation-free rule: __device__ globals)
__device__ float g_qp[BB * TT * EE];            // projected+scaled Q  [B,T,E]
__device__ float g_kp[BB * SS * EE];            // projected K         [B,S,E]
__device__ float g_vp[BB * SS * EE];            // projected V         [B,S,E]
__device__ float g_att[BB * TT * EE];           // attention output    [B,T,E]

// ---------------------------------------------------------------------------
// C[M,256] = (X[M,256] @ W^T + bias) * scale      (torch Linear convention,
// W is [out=256, in=256] row-major). M must be a multiple of 128.
// 128x128 block tile, 256 threads, 8x8 micro-tile, BK=8.
// ---------------------------------------------------------------------------
__global__ __launch_bounds__(256, 2)
void gemm_proj_kernel(const float* __restrict__ X, const float* __restrict__ W,
                      const float* __restrict__ bias, float* __restrict__ C,
                      int M, float scale)
{
    const int K = EE, N = EE;
    __shared__ float As[8][128];   // transposed: As[k][m]
    __shared__ float Bs[8][128];   // transposed: Bs[k][n]

    const int tid = threadIdx.x;
    const int tx  = tid & 15;      // n micro-block
    const int ty  = tid >> 4;      // m micro-block
    const int m0  = blockIdx.y * 128;
    const int n0  = blockIdx.x * 128;

    float acc[8][8];
#pragma unroll
    for (int i = 0; i < 8; i++)
#pragma unroll
        for (int j = 0; j < 8; j++) acc[i][j] = 0.f;

    const int lm = tid >> 1;             // 0..127 (row within tile)
    const int lk = (tid & 1) * 4;        // 0 or 4 (k offset)
    const float* Xp = X + (size_t)(m0 + lm) * K + lk;
    const float* Wp = W + (size_t)(n0 + lm) * K + lk;

    for (int k0 = 0; k0 < K; k0 += 8) {
        const float4 xa = *(const float4*)(Xp + k0);
        const float4 wb = *(const float4*)(Wp + k0);
        __syncthreads();
        As[lk + 0][lm] = xa.x; As[lk + 1][lm] = xa.y;
        As[lk + 2][lm] = xa.z; As[lk + 3][lm] = xa.w;
        Bs[lk + 0][lm] = wb.x; Bs[lk + 1][lm] = wb.y;
        Bs[lk + 2][lm] = wb.z; Bs[lk + 3][lm] = wb.w;
        __syncthreads();
#pragma unroll
        for (int kk = 0; kk < 8; kk++) {
            float a[8], b[8];
            *(float4*)&a[0] = *(const float4*)&As[kk][ty * 8];
            *(float4*)&a[4] = *(const float4*)&As[kk][ty * 8 + 4];
            *(float4*)&b[0] = *(const float4*)&Bs[kk][tx * 8];
            *(float4*)&b[4] = *(const float4*)&Bs[kk][tx * 8 + 4];
#pragma unroll
            for (int i = 0; i < 8; i++)
#pragma unroll
                for (int j = 0; j < 8; j++)
                    acc[i][j] = fmaf(a[i], b[j], acc[i][j]);
        }
    }

    float bv[8];
#pragma unroll
    for (int j = 0; j < 8; j++) bv[j] = bias[n0 + tx * 8 + j];

#pragma unroll
    for (int i = 0; i < 8; i++) {
        const int row = m0 + ty * 8 + i;
        float4 r0, r1;
        r0.x = (acc[i][0] + bv[0]) * scale;
        r0.y = (acc[i][1] + bv[1]) * scale;
        r0.z = (acc[i][2] + bv[2]) * scale;
        r0.w = (acc[i][3] + bv[3]) * scale;
        r1.x = (acc[i][4] + bv[4]) * scale;
        r1.y = (acc[i][5] + bv[5]) * scale;
        r1.z = (acc[i][6] + bv[6]) * scale;
        r1.w = (acc[i][7] + bv[7]) * scale;
        *(float4*)&C[(size_t)row * N + n0 + tx * 8]     = r0;
        *(float4*)&C[(size_t)row * N + n0 + tx * 8 + 4] = r1;
    }
}

// ---------------------------------------------------------------------------
// Flash attention, fp32. One block per (b, h, 64-query tile). 256 threads.
// Q is pre-scaled by 1/sqrt(D). Bias = mask[b,t,s] * sf[h] added to scores.
// Online softmax over S in chunks of 64.
// Thread layout: x = tid&15 (s / d columns), y = tid>>4 (q rows, strided 16).
// ---------------------------------------------------------------------------
__global__ __launch_bounds__(256)
void flash_attn_kernel(const float* __restrict__ qp, const float* __restrict__ kp,
                       const float* __restrict__ vp, const float* __restrict__ mask,
                       const float* __restrict__ sf, float* __restrict__ outp)
{
    __shared__ float qs[64][36];   // pad 36: float4-aligned rows, low conflict
    __shared__ float ks[64][36];
    __shared__ float vs[64][32];
    __shared__ float ps[64][68];   // pad 68: float4-aligned rows

    const int h  = blockIdx.x;
    const int tq = blockIdx.y;
    const int b  = blockIdx.z;
    const int t0 = tq * 64;
    const int tid = threadIdx.x;
    const int x = tid & 15;
    const int y = tid >> 4;
    const float sfh = sf[h];

    const float* qbase = qp + ((size_t)b * TT + t0) * EE + h * DD;
    const float* kbase = kp + (size_t)b * SS * EE + h * DD;
    const float* vbase = vp + (size_t)b * SS * EE + h * DD;
    const float* mbase = mask + ((size_t)b * TT + t0) * (size_t)SS;

    // load Q tile (64 x 32) via float4
#pragma unroll
    for (int u = 0; u < 2; u++) {
        const int idx = tid + u * 256;        // float4 index, 512 total
        const int r  = idx >> 3;
        const int c4 = (idx & 7) * 4;
        const float4 v = *(const float4*)(qbase + (size_t)r * EE + c4);
        *(float4*)&qs[r][c4] = v;
    }

    float m_i[4], l_i[4], o0[4], o1[4];
#pragma unroll
    for (int i = 0; i < 4; i++) { m_i[i] = -1e30f; l_i[i] = 0.f; o0[i] = 0.f; o1[i] = 0.f; }

    for (int s0 = 0; s0 < SS; s0 += 64) {
        // load K/V chunk (64 x 32 each) via float4
#pragma unroll
        for (int u = 0; u < 2; u++) {
            const int idx = tid + u * 256;
            const int r  = idx >> 3;
            const int c4 = (idx & 7) * 4;
            const float4 kv = *(const float4*)(kbase + (size_t)(s0 + r) * EE + c4);
            const float4 vv = *(const float4*)(vbase + (size_t)(s0 + r) * EE + c4);
            *(float4*)&ks[r][c4] = kv;
            *(float4*)&vs[r][c4] = vv;
        }
        __syncthreads();

        // scores: 4q x 4s micro-tile, q rows y+16i, s cols x+16j
        float acc[4][4];
#pragma unroll
        for (int i = 0; i < 4; i++)
#pragma unroll
            for (int j = 0; j < 4; j++) acc[i][j] = 0.f;

#pragma unroll
        for (int d = 0; d < 32; d += 4) {
            float4 a[4], bb[4];
#pragma unroll
            for (int i = 0; i < 4; i++) a[i]  = *(const float4*)&qs[y + 16 * i][d];
#pragma unroll
            for (int j = 0; j < 4; j++) bb[j] = *(const float4*)&ks[x + 16 * j][d];
#pragma unroll
            for (int i = 0; i < 4; i++)
#pragma unroll
                for (int j = 0; j < 4; j++) {
                    acc[i][j] = fmaf(a[i].x, bb[j].x, acc[i][j]);
                    acc[i][j] = fmaf(a[i].y, bb[j].y, acc[i][j]);
                    acc[i][j] = fmaf(a[i].z, bb[j].z, acc[i][j]);
                    acc[i][j] = fmaf(a[i].w, bb[j].w, acc[i][j]);
                }
        }

        // bias + online softmax (row groups = 16 lanes sharing y)
#pragma unroll
        for (int i = 0; i < 4; i++) {
            const float* mrow = mbase + (size_t)(y + 16 * i) * SS + s0 + x;
#pragma unroll
            for (int j = 0; j < 4; j++)
                acc[i][j] = fmaf(mrow[16 * j], sfh, acc[i][j]);

            float rm = fmaxf(fmaxf(acc[i][0], acc[i][1]), fmaxf(acc[i][2], acc[i][3]));
            rm = fmaxf(rm, __shfl_xor_sync(0xFFFFFFFFu, rm, 1));
            rm = fmaxf(rm, __shfl_xor_sync(0xFFFFFFFFu, rm, 2));
            rm = fmaxf(rm, __shfl_xor_sync(0xFFFFFFFFu, rm, 4));
            rm = fmaxf(rm, __shfl_xor_sync(0xFFFFFFFFu, rm, 8));

            const float mn = fmaxf(m_i[i], rm);
            const float al = __expf(m_i[i] - mn);
            m_i[i] = mn;

            float rs = 0.f;
#pragma unroll
            for (int j = 0; j < 4; j++) {
                const float p = __expf(acc[i][j] - mn);
                ps[y + 16 * i][x + 16 * j] = p;
                rs += p;
            }
            rs += __shfl_xor_sync(0xFFFFFFFFu, rs, 1);
            rs += __shfl_xor_sync(0xFFFFFFFFu, rs, 2);
            rs += __shfl_xor_sync(0xFFFFFFFFu, rs, 4);
            rs += __shfl_xor_sync(0xFFFFFFFFu, rs, 8);

            l_i[i] = l_i[i] * al + rs;
            o0[i] *= al;
            o1[i] *= al;
        }
        __syncthreads();   // ps fully written

        // PV: o[q, 2x..2x+1] += sum_s p[q][s] * v[s][2x..2x+1]
#pragma unroll 4
        for (int s = 0; s < 64; s += 4) {
            float4 p4[4];
#pragma unroll
            for (int i = 0; i < 4; i++) p4[i] = *(const float4*)&ps[y + 16 * i][s];
#pragma unroll
            for (int u = 0; u < 4; u++) {
                const float2 v = *(const float2*)&vs[s + u][x * 2];
#pragma unroll
                for (int i = 0; i < 4; i++) {
                    const float p = ((const float*)&p4[i])[u];
                    o0[i] = fmaf(p, v.x, o0[i]);
                    o1[i] = fmaf(p, v.y, o1[i]);
                }
            }
        }
        __syncthreads();   // done with ks/vs/ps before next chunk overwrites
    }

    // epilogue: normalize and store to [B,T,E] with e = h*32 + 2x {+1}
    float* obase = outp + ((size_t)b * TT + t0) * EE + h * DD;
#pragma unroll
    for (int i = 0; i < 4; i++) {
        const float inv = 1.f / l_i[i];
        float2 r;
        r.x = o0[i] * inv;
        r.y = o1[i] * inv;
        *(float2*)&obase[(size_t)(y + 16 * i) * EE + x * 2] = r;
    }
}

// ---------------------------------------------------------------------------
// Launch: Q/K/V projections -> flash attention -> output projection.
// 5 kernel launches, no sync / alloc / memcpy -> graph-capturable.
// ---------------------------------------------------------------------------
extern "C" void kernel_launch(void* const* d_in, const int* in_sizes, int n_in,
                              void* d_out, int out_size)
{
    (void)in_sizes; (void)n_in; (void)out_size;

    const float* query = (const float*)d_in[0];
    const float* key   = (const float*)d_in[1];
    const float* value = (const float*)d_in[2];
    const float* mask  = (const float*)d_in[3];
    const float* Wq    = (const float*)d_in[4];
    const float* bq    = (const float*)d_in[5];
    const float* Wk    = (const float*)d_in[6];
    const float* bk    = (const float*)d_in[7];
    const float* Wv    = (const float*)d_in[8];
    const float* bv    = (const float*)d_in[9];
    const float* Wo    = (const float*)d_in[10];
    const float* bo    = (const float*)d_in[11];
    const float* sf    = (const float*)d_in[12];
    float* out = (float*)d_out;

    float *qp = nullptr, *kp = nullptr, *vp = nullptr, *att = nullptr;
    cudaGetSymbolAddress((void**)&qp,  g_qp);
    cudaGetSymbolAddress((void**)&kp,  g_kp);
    cudaGetSymbolAddress((void**)&vp,  g_vp);
    cudaGetSymbolAddress((void**)&att, g_att);

    const float qscale = 0.17677669529663687f;  // 1/sqrt(D), folded into Q proj
    const dim3 blk(256);

    gemm_proj_kernel<<<dim3(2, (BB * TT) / 128), blk>>>(query, Wq, bq, qp, BB * TT, qscale);
    gemm_proj_kernel<<<dim3(2, (BB * SS) / 128), blk>>>(key,   Wk, bk, kp, BB * SS, 1.0f);
    gemm_proj_kernel<<<dim3(2, (BB * SS) / 128), blk>>>(value, Wv, bv, vp, BB * SS, 1.0f);

    flash_attn_kernel<<<dim3(HH, TT / 64, BB), blk>>>(qp, kp, vp, mask, sf, att);

    gemm_proj_kernel<<<dim3(2, (BB * TT) / 128), blk>>>(att, Wo, bo, out, BB * TT, 1.0f);
}

// round 7
// speedup vs baseline: 1.3680x; 1.3680x over previous
#include <cuda_runtime.h>
#include <math.h>

// Problem constants (fixed by the reference)
#define BB 4
#define TT 256
#define SS 16384
#define EE 256
#define HH 8
#define DD 32

#define SPLITS 8
#define SCHUNK (SS / SPLITS)          // 2048 keys per block
#define NTQ (TT / 64)                 // 4 query tiles
#define NPID (BB * NTQ * HH * SPLITS) // 1024 partials

// Scratch (allocation-free rule: __device__ globals)
__device__ float g_qp[BB * TT * EE];            // projected+scaled Q  [B,T,E]
__device__ float g_kp[BB * SS * EE];            // projected K         [B,S,E]
__device__ float g_vp[BB * SS * EE];            // projected V         [B,S,E]
__device__ float g_att[BB * TT * EE];           // attention output    [B,T,E]
__device__ float g_po[NPID * 64 * 32];          // unnormalized partial O
__device__ float g_pm[NPID * 64];               // partial row max
__device__ float g_pl[NPID * 64];               // partial row sum

// ---------------------------------------------------------------------------
// C[M,256] = (X[M,256] @ W^T + bias) * scale      (torch Linear convention,
// W is [out=256, in=256] row-major). M must be a multiple of 128.
// 128x128 block tile, 256 threads, 8x8 micro-tile, BK=8.
// ---------------------------------------------------------------------------
__global__ __launch_bounds__(256, 2)
void gemm_proj_kernel(const float* __restrict__ X, const float* __restrict__ W,
                      const float* __restrict__ bias, float* __restrict__ C,
                      int M, float scale)
{
    const int K = EE, N = EE;
    __shared__ float As[8][128];   // transposed: As[k][m]
    __shared__ float Bs[8][128];   // transposed: Bs[k][n]

    const int tid = threadIdx.x;
    const int tx  = tid & 15;      // n micro-block
    const int ty  = tid >> 4;      // m micro-block
    const int m0  = blockIdx.y * 128;
    const int n0  = blockIdx.x * 128;

    float acc[8][8];
#pragma unroll
    for (int i = 0; i < 8; i++)
#pragma unroll
        for (int j = 0; j < 8; j++) acc[i][j] = 0.f;

    const int lm = tid >> 1;             // 0..127 (row within tile)
    const int lk = (tid & 1) * 4;        // 0 or 4 (k offset)
    const float* Xp = X + (size_t)(m0 + lm) * K + lk;
    const float* Wp = W + (size_t)(n0 + lm) * K + lk;

    for (int k0 = 0; k0 < K; k0 += 8) {
        const float4 xa = *(const float4*)(Xp + k0);
        const float4 wb = *(const float4*)(Wp + k0);
        __syncthreads();
        As[lk + 0][lm] = xa.x; As[lk + 1][lm] = xa.y;
        As[lk + 2][lm] = xa.z; As[lk + 3][lm] = xa.w;
        Bs[lk + 0][lm] = wb.x; Bs[lk + 1][lm] = wb.y;
        Bs[lk + 2][lm] = wb.z; Bs[lk + 3][lm] = wb.w;
        __syncthreads();
#pragma unroll
        for (int kk = 0; kk < 8; kk++) {
            float a[8], b[8];
            *(float4*)&a[0] = *(const float4*)&As[kk][ty * 8];
            *(float4*)&a[4] = *(const float4*)&As[kk][ty * 8 + 4];
            *(float4*)&b[0] = *(const float4*)&Bs[kk][tx * 8];
            *(float4*)&b[4] = *(const float4*)&Bs[kk][tx * 8 + 4];
#pragma unroll
            for (int i = 0; i < 8; i++)
#pragma unroll
                for (int j = 0; j < 8; j++)
                    acc[i][j] = fmaf(a[i], b[j], acc[i][j]);
        }
    }

    float bv[8];
#pragma unroll
    for (int j = 0; j < 8; j++) bv[j] = bias[n0 + tx * 8 + j];

#pragma unroll
    for (int i = 0; i < 8; i++) {
        const int row = m0 + ty * 8 + i;
        float4 r0, r1;
        r0.x = (acc[i][0] + bv[0]) * scale;
        r0.y = (acc[i][1] + bv[1]) * scale;
        r0.z = (acc[i][2] + bv[2]) * scale;
        r0.w = (acc[i][3] + bv[3]) * scale;
        r1.x = (acc[i][4] + bv[4]) * scale;
        r1.y = (acc[i][5] + bv[5]) * scale;
        r1.z = (acc[i][6] + bv[6]) * scale;
        r1.w = (acc[i][7] + bv[7]) * scale;
        *(float4*)&C[(size_t)row * N + n0 + tx * 8]     = r0;
        *(float4*)&C[(size_t)row * N + n0 + tx * 8 + 4] = r1;
    }
}

// ---------------------------------------------------------------------------
// Split-KV flash attention, fp32. One block per (b, h, 64-query tile, split).
// 256 threads, 3 CTAs/SM. Q pre-scaled by 1/sqrt(D). Each block covers
// SCHUNK keys and writes an unnormalized partial (O, m, l) to scratch.
// Thread layout: x = tid&15 (s / d columns), y = tid>>4 (q rows, strided 16).
// ---------------------------------------------------------------------------
__global__ __launch_bounds__(256, 3)
void flash_attn_kernel(const float* __restrict__ qp, const float* __restrict__ kp,
                       const float* __restrict__ vp, const float* __restrict__ mask,
                       const float* __restrict__ sf)
{
    __shared__ float qs[64][36];   // pad 36: float4-aligned rows, low conflict
    __shared__ float ks[64][36];
    __shared__ float vs[64][32];
    __shared__ float ps[64][68];   // pad 68: float4-aligned rows

    const int h     = blockIdx.x & 7;
    const int split = blockIdx.x >> 3;
    const int tq = blockIdx.y;
    const int b  = blockIdx.z;
    const int t0 = tq * 64;
    const int s_begin = split * SCHUNK;
    const int tid = threadIdx.x;
    const int x = tid & 15;
    const int y = tid >> 4;
    const float sfh = sf[h];

    const float* qbase = qp + ((size_t)b * TT + t0) * EE + h * DD;
    const float* kbase = kp + (size_t)b * SS * EE + h * DD;
    const float* vbase = vp + (size_t)b * SS * EE + h * DD;
    const float* mbase = mask + ((size_t)b * TT + t0) * (size_t)SS;

    // load Q tile (64 x 32) via float4
#pragma unroll
    for (int u = 0; u < 2; u++) {
        const int idx = tid + u * 256;        // float4 index, 512 total
        const int r  = idx >> 3;
        const int c4 = (idx & 7) * 4;
        const float4 v = *(const float4*)(qbase + (size_t)r * EE + c4);
        *(float4*)&qs[r][c4] = v;
    }

    float m_i[4], l_i[4], o0[4], o1[4];
#pragma unroll
    for (int i = 0; i < 4; i++) { m_i[i] = -1e30f; l_i[i] = 0.f; o0[i] = 0.f; o1[i] = 0.f; }

    for (int s0 = s_begin; s0 < s_begin + SCHUNK; s0 += 64) {
        // load K/V chunk (64 x 32 each) via float4
#pragma unroll
        for (int u = 0; u < 2; u++) {
            const int idx = tid + u * 256;
            const int r  = idx >> 3;
            const int c4 = (idx & 7) * 4;
            const float4 kv = *(const float4*)(kbase + (size_t)(s0 + r) * EE + c4);
            const float4 vv = *(const float4*)(vbase + (size_t)(s0 + r) * EE + c4);
            *(float4*)&ks[r][c4] = kv;
            *(float4*)&vs[r][c4] = vv;
        }
        __syncthreads();

        // scores: 4q x 4s micro-tile, q rows y+16i, s cols x+16j
        float acc[4][4];
#pragma unroll
        for (int i = 0; i < 4; i++)
#pragma unroll
            for (int j = 0; j < 4; j++) acc[i][j] = 0.f;

#pragma unroll
        for (int d = 0; d < 32; d += 4) {
            float4 a[4], bb[4];
#pragma unroll
            for (int i = 0; i < 4; i++) a[i]  = *(const float4*)&qs[y + 16 * i][d];
#pragma unroll
            for (int j = 0; j < 4; j++) bb[j] = *(const float4*)&ks[x + 16 * j][d];
#pragma unroll
            for (int i = 0; i < 4; i++)
#pragma unroll
                for (int j = 0; j < 4; j++) {
                    acc[i][j] = fmaf(a[i].x, bb[j].x, acc[i][j]);
                    acc[i][j] = fmaf(a[i].y, bb[j].y, acc[i][j]);
                    acc[i][j] = fmaf(a[i].z, bb[j].z, acc[i][j]);
                    acc[i][j] = fmaf(a[i].w, bb[j].w, acc[i][j]);
                }
        }

        // bias + online softmax (row groups = 16 lanes sharing y)
#pragma unroll
        for (int i = 0; i < 4; i++) {
            const float* mrow = mbase + (size_t)(y + 16 * i) * SS + s0 + x;
#pragma unroll
            for (int j = 0; j < 4; j++)
                acc[i][j] = fmaf(mrow[16 * j], sfh, acc[i][j]);

            float rm = fmaxf(fmaxf(acc[i][0], acc[i][1]), fmaxf(acc[i][2], acc[i][3]));
            rm = fmaxf(rm, __shfl_xor_sync(0xFFFFFFFFu, rm, 1));
            rm = fmaxf(rm, __shfl_xor_sync(0xFFFFFFFFu, rm, 2));
            rm = fmaxf(rm, __shfl_xor_sync(0xFFFFFFFFu, rm, 4));
            rm = fmaxf(rm, __shfl_xor_sync(0xFFFFFFFFu, rm, 8));

            const float mn = fmaxf(m_i[i], rm);
            const float al = __expf(m_i[i] - mn);
            m_i[i] = mn;

            float rs = 0.f;
#pragma unroll
            for (int j = 0; j < 4; j++) {
                const float p = __expf(acc[i][j] - mn);
                ps[y + 16 * i][x + 16 * j] = p;
                rs += p;
            }
            rs += __shfl_xor_sync(0xFFFFFFFFu, rs, 1);
            rs += __shfl_xor_sync(0xFFFFFFFFu, rs, 2);
            rs += __shfl_xor_sync(0xFFFFFFFFu, rs, 4);
            rs += __shfl_xor_sync(0xFFFFFFFFu, rs, 8);

            l_i[i] = l_i[i] * al + rs;
            o0[i] *= al;
            o1[i] *= al;
        }
        __syncthreads();   // ps fully written

        // PV: o[q, 2x..2x+1] += sum_s p[q][s] * v[s][2x..2x+1]
#pragma unroll 4
        for (int s = 0; s < 64; s += 4) {
            float4 p4[4];
#pragma unroll
            for (int i = 0; i < 4; i++) p4[i] = *(const float4*)&ps[y + 16 * i][s];
#pragma unroll
            for (int u = 0; u < 4; u++) {
                const float2 v = *(const float2*)&vs[s + u][x * 2];
#pragma unroll
                for (int i = 0; i < 4; i++) {
                    const float p = ((const float*)&p4[i])[u];
                    o0[i] = fmaf(p, v.x, o0[i]);
                    o1[i] = fmaf(p, v.y, o1[i]);
                }
            }
        }
        __syncthreads();   // done with ks/vs/ps before next chunk overwrites
    }

    // epilogue: write unnormalized partials (O, m, l) to scratch
    const int pid = (((b * NTQ + tq) * HH + h) * SPLITS + split);
    float* pob = g_po + (size_t)pid * (64 * 32);
#pragma unroll
    for (int i = 0; i < 4; i++) {
        const int row = y + 16 * i;
        float2 r; r.x = o0[i]; r.y = o1[i];
        *(float2*)&pob[row * 32 + x * 2] = r;
        if (x == 0) {
            g_pm[pid * 64 + row] = m_i[i];
            g_pl[pid * 64 + row] = l_i[i];
        }
    }
}

// ---------------------------------------------------------------------------
// Combine SPLITS partials per (b, tq, h): log-sum-exp rescale + normalize.
// Grid = 128 blocks (one per (b,tq,h)), 256 threads: thread handles
// row = tid>>2 and 8 d-columns.
// ---------------------------------------------------------------------------
__global__ __launch_bounds__(256)
void flash_combine_kernel(float* __restrict__ outp)
{
    const int g = blockIdx.x;                 // ((b*NTQ + tq)*HH + h)
    const int h  = g & 7;
    const int tq = (g >> 3) & 3;
    const int b  = g >> 5;
    const int base = g * SPLITS;

    const int tid = threadIdx.x;
    const int row = tid >> 2;                 // 0..63
    const int d0  = (tid & 3) * 8;            // 0,8,16,24

    float m[SPLITS], l[SPLITS];
    float M = -1e30f;
#pragma unroll
    for (int s = 0; s < SPLITS; s++) {
        m[s] = g_pm[(base + s) * 64 + row];
        l[s] = g_pl[(base + s) * 64 + row];
        M = fmaxf(M, m[s]);
    }
    float L = 0.f;
    float w[SPLITS];
#pragma unroll
    for (int s = 0; s < SPLITS; s++) {
        w[s] = __expf(m[s] - M);
        L += w[s] * l[s];
    }
    const float inv = 1.f / L;

    float acc[8];
#pragma unroll
    for (int j = 0; j < 8; j++) acc[j] = 0.f;
#pragma unroll
    for (int s = 0; s < SPLITS; s++) {
        const float* p = g_po + (size_t)(base + s) * (64 * 32) + row * 32 + d0;
        const float4 a = *(const float4*)(p);
        const float4 c = *(const float4*)(p + 4);
        acc[0] = fmaf(w[s], a.x, acc[0]); acc[1] = fmaf(w[s], a.y, acc[1]);
        acc[2] = fmaf(w[s], a.z, acc[2]); acc[3] = fmaf(w[s], a.w, acc[3]);
        acc[4] = fmaf(w[s], c.x, acc[4]); acc[5] = fmaf(w[s], c.y, acc[5]);
        acc[6] = fmaf(w[s], c.z, acc[6]); acc[7] = fmaf(w[s], c.w, acc[7]);
    }

    float* ob = outp + ((size_t)b * TT + tq * 64 + row) * EE + h * DD + d0;
    float4 r0, r1;
    r0.x = acc[0] * inv; r0.y = acc[1] * inv; r0.z = acc[2] * inv; r0.w = acc[3] * inv;
    r1.x = acc[4] * inv; r1.y = acc[5] * inv; r1.z = acc[6] * inv; r1.w = acc[7] * inv;
    *(float4*)ob       = r0;
    *(float4*)(ob + 4) = r1;
}

// ---------------------------------------------------------------------------
// Launch: Q/K/V projections -> split-KV flash -> combine -> output projection.
// 6 kernel launches, no sync / alloc / memcpy -> graph-capturable.
// ---------------------------------------------------------------------------
extern "C" void kernel_launch(void* const* d_in, const int* in_sizes, int n_in,
                              void* d_out, int out_size)
{
    (void)in_sizes; (void)n_in; (void)out_size;

    const float* query = (const float*)d_in[0];
    const float* key   = (const float*)d_in[1];
    const float* value = (const float*)d_in[2];
    const float* mask  = (const float*)d_in[3];
    const float* Wq    = (const float*)d_in[4];
    const float* bq    = (const float*)d_in[5];
    const float* Wk    = (const float*)d_in[6];
    const float* bk    = (const float*)d_in[7];
    const float* Wv    = (const float*)d_in[8];
    const float* bv    = (const float*)d_in[9];
    const float* Wo    = (const float*)d_in[10];
    const float* bo    = (const float*)d_in[11];
    const float* sf    = (const float*)d_in[12];
    float* out = (float*)d_out;

    float *qp = nullptr, *kp = nullptr, *vp = nullptr, *att = nullptr;
    cudaGetSymbolAddress((void**)&qp,  g_qp);
    cudaGetSymbolAddress((void**)&kp,  g_kp);
    cudaGetSymbolAddress((void**)&vp,  g_vp);
    cudaGetSymbolAddress((void**)&att, g_att);

    const float qscale = 0.17677669529663687f;  // 1/sqrt(D), folded into Q proj
    const dim3 blk(256);

    gemm_proj_kernel<<<dim3(2, (BB * TT) / 128), blk>>>(query, Wq, bq, qp, BB * TT, qscale);
    gemm_proj_kernel<<<dim3(2, (BB * SS) / 128), blk>>>(key,   Wk, bk, kp, BB * SS, 1.0f);
    gemm_proj_kernel<<<dim3(2, (BB * SS) / 128), blk>>>(value, Wv, bv, vp, BB * SS, 1.0f);

    flash_attn_kernel<<<dim3(HH * SPLITS, NTQ, BB), blk>>>(qp, kp, vp, mask, sf);
    flash_combine_kernel<<<dim3(BB * NTQ * HH), blk>>>(att);

    gemm_proj_kernel<<<dim3(2, (BB * TT) / 128), blk>>>(att, Wo, bo, out, BB * TT, 1.0f);
}

// round 8
// speedup vs baseline: 1.5644x; 1.1436x over previous
#include <cuda_runtime.h>
#include <math.h>

// Problem constants (fixed by the reference)
#define BB 4
#define TT 256
#define SS 16384
#define EE 256
#define HH 8
#define DD 32

#define SPLITS 16
#define SCHUNK (SS / SPLITS)          // 1024 keys per block
#define NTQ (TT / 64)                 // 4 query tiles
#define NPID (BB * NTQ * HH * SPLITS) // 2048 partials

// Scratch (allocation-free rule: __device__ globals)
__device__ float g_qp[BB * TT * EE];            // projected+scaled Q  [B,T,E]
__device__ float g_kp[BB * SS * EE];            // projected K         [B,S,E]
__device__ float g_vp[BB * SS * EE];            // projected V         [B,S,E]
__device__ float g_att[BB * TT * EE];           // attention output    [B,T,E]
__device__ float g_po[NPID * 64 * 32];          // unnormalized partial O
__device__ float g_pl[NPID * 64];               // partial row sum

// ---------------------------------------------------------------------------
// C[M,256] = (X[M,256] @ W^T + bias) * scale. 128x128 tile, 256 thr, 8x8 micro.
// Used for the two big (M=65536) K/V projections.
// ---------------------------------------------------------------------------
__global__ __launch_bounds__(256, 2)
void gemm_proj_kernel(const float* __restrict__ X, const float* __restrict__ W,
                      const float* __restrict__ bias, float* __restrict__ C,
                      int M, float scale)
{
    const int K = EE, N = EE;
    __shared__ float As[8][128];   // transposed: As[k][m]
    __shared__ float Bs[8][128];   // transposed: Bs[k][n]

    const int tid = threadIdx.x;
    const int tx  = tid & 15;
    const int ty  = tid >> 4;
    const int m0  = blockIdx.y * 128;
    const int n0  = blockIdx.x * 128;

    float acc[8][8];
#pragma unroll
    for (int i = 0; i < 8; i++)
#pragma unroll
        for (int j = 0; j < 8; j++) acc[i][j] = 0.f;

    const int lm = tid >> 1;
    const int lk = (tid & 1) * 4;
    const float* Xp = X + (size_t)(m0 + lm) * K + lk;
    const float* Wp = W + (size_t)(n0 + lm) * K + lk;

    for (int k0 = 0; k0 < K; k0 += 8) {
        const float4 xa = *(const float4*)(Xp + k0);
        const float4 wb = *(const float4*)(Wp + k0);
        __syncthreads();
        As[lk + 0][lm] = xa.x; As[lk + 1][lm] = xa.y;
        As[lk + 2][lm] = xa.z; As[lk + 3][lm] = xa.w;
        Bs[lk + 0][lm] = wb.x; Bs[lk + 1][lm] = wb.y;
        Bs[lk + 2][lm] = wb.z; Bs[lk + 3][lm] = wb.w;
        __syncthreads();
#pragma unroll
        for (int kk = 0; kk < 8; kk++) {
            float a[8], b[8];
            *(float4*)&a[0] = *(const float4*)&As[kk][ty * 8];
            *(float4*)&a[4] = *(const float4*)&As[kk][ty * 8 + 4];
            *(float4*)&b[0] = *(const float4*)&Bs[kk][tx * 8];
            *(float4*)&b[4] = *(const float4*)&Bs[kk][tx * 8 + 4];
#pragma unroll
            for (int i = 0; i < 8; i++)
#pragma unroll
                for (int j = 0; j < 8; j++)
                    acc[i][j] = fmaf(a[i], b[j], acc[i][j]);
        }
    }

    float bv[8];
#pragma unroll
    for (int j = 0; j < 8; j++) bv[j] = bias[n0 + tx * 8 + j];

#pragma unroll
    for (int i = 0; i < 8; i++) {
        const int row = m0 + ty * 8 + i;
        float4 r0, r1;
        r0.x = (acc[i][0] + bv[0]) * scale;
        r0.y = (acc[i][1] + bv[1]) * scale;
        r0.z = (acc[i][2] + bv[2]) * scale;
        r0.w = (acc[i][3] + bv[3]) * scale;
        r1.x = (acc[i][4] + bv[4]) * scale;
        r1.y = (acc[i][5] + bv[5]) * scale;
        r1.z = (acc[i][6] + bv[6]) * scale;
        r1.w = (acc[i][7] + bv[7]) * scale;
        *(float4*)&C[(size_t)row * N + n0 + tx * 8]     = r0;
        *(float4*)&C[(size_t)row * N + n0 + tx * 8 + 4] = r1;
    }
}

// ---------------------------------------------------------------------------
// Small-M GEMM: 64x64 tile, 4x4 micro, BK=16. For M=1024 projections
// (Q proj, out proj) -> 64 blocks instead of 16 -> much better SM coverage.
// ---------------------------------------------------------------------------
__global__ __launch_bounds__(256)
void gemm64_kernel(const float* __restrict__ X, const float* __restrict__ W,
                   const float* __restrict__ bias, float* __restrict__ C,
                   float scale)
{
    const int K = EE, N = EE;
    __shared__ float As[16][64];
    __shared__ float Bs[16][64];

    const int tid = threadIdx.x;
    const int tx  = tid & 15;
    const int ty  = tid >> 4;
    const int m0  = blockIdx.y * 64;
    const int n0  = blockIdx.x * 64;

    float acc[4][4];
#pragma unroll
    for (int i = 0; i < 4; i++)
#pragma unroll
        for (int j = 0; j < 4; j++) acc[i][j] = 0.f;

    const int lm = tid >> 2;             // 0..63
    const int lk = (tid & 3) * 4;        // 0,4,8,12
    const float* Xp = X + (size_t)(m0 + lm) * K + lk;
    const float* Wp = W + (size_t)(n0 + lm) * K + lk;

    for (int k0 = 0; k0 < K; k0 += 16) {
        const float4 xa = *(const float4*)(Xp + k0);
        const float4 wb = *(const float4*)(Wp + k0);
        __syncthreads();
        As[lk + 0][lm] = xa.x; As[lk + 1][lm] = xa.y;
        As[lk + 2][lm] = xa.z; As[lk + 3][lm] = xa.w;
        Bs[lk + 0][lm] = wb.x; Bs[lk + 1][lm] = wb.y;
        Bs[lk + 2][lm] = wb.z; Bs[lk + 3][lm] = wb.w;
        __syncthreads();
#pragma unroll
        for (int kk = 0; kk < 16; kk++) {
            float4 a = *(const float4*)&As[kk][ty * 4];
            float4 b = *(const float4*)&Bs[kk][tx * 4];
            const float av[4] = {a.x, a.y, a.z, a.w};
            const float bw[4] = {b.x, b.y, b.z, b.w};
#pragma unroll
            for (int i = 0; i < 4; i++)
#pragma unroll
                for (int j = 0; j < 4; j++)
                    acc[i][j] = fmaf(av[i], bw[j], acc[i][j]);
        }
    }

    float bv[4];
#pragma unroll
    for (int j = 0; j < 4; j++) bv[j] = bias[n0 + tx * 4 + j];

#pragma unroll
    for (int i = 0; i < 4; i++) {
        const int row = m0 + ty * 4 + i;
        float4 r;
        r.x = (acc[i][0] + bv[0]) * scale;
        r.y = (acc[i][1] + bv[1]) * scale;
        r.z = (acc[i][2] + bv[2]) * scale;
        r.w = (acc[i][3] + bv[3]) * scale;
        *(float4*)&C[(size_t)row * N + n0 + tx * 4] = r;
    }
}

// ---------------------------------------------------------------------------
// Split-KV flash attention, fp32, STATIC softmax max (m == sf[h]; bounded
// scores make exp(score - sf[h]) overflow-free, softmax stays exact).
// One block per (b, h, 64-query tile, split). 256 threads, 3 CTAs/SM.
// QK mapping:  x = tid&15 (s cols, stride 16), y = tid>>4 (q rows, stride 16)
// PV mapping:  sh = tid>>7 (s half), qg = (tid>>3)&15 (q rows, stride 16),
//              xd = tid&7 (d group of 4) -> float4 v loads, 8 FMA/LDS.
// ---------------------------------------------------------------------------
__global__ __launch_bounds__(256, 3)
void flash_attn_kernel(const float* __restrict__ qp, const float* __restrict__ kp,
                       const float* __restrict__ vp, const float* __restrict__ mask,
                       const float* __restrict__ sf)
{
    __shared__ float qs[64][36];
    __shared__ float ks[64][36];
    __shared__ float vs[64][32];
    __shared__ float ps[64][68];

    const int h     = blockIdx.x & 7;
    const int split = blockIdx.x >> 3;
    const int tq = blockIdx.y;
    const int b  = blockIdx.z;
    const int t0 = tq * 64;
    const int s_begin = split * SCHUNK;
    const int tid = threadIdx.x;
    const int x  = tid & 15;
    const int y  = tid >> 4;
    const int sh = tid >> 7;        // 0/1: which 32-key half this thread owns in PV
    const int qg = (tid >> 3) & 15; // PV q rows: qg + 16*i
    const int xd = tid & 7;         // PV d cols: 4*xd .. 4*xd+3
    const float sfh = sf[h];

    const float* qbase = qp + ((size_t)b * TT + t0) * EE + h * DD;
    const float* kbase = kp + (size_t)b * SS * EE + h * DD;
    const float* vbase = vp + (size_t)b * SS * EE + h * DD;
    const float* mbase = mask + ((size_t)b * TT + t0) * (size_t)SS;

    // load Q tile (64 x 32) via float4
#pragma unroll
    for (int u = 0; u < 2; u++) {
        const int idx = tid + u * 256;
        const int r  = idx >> 3;
        const int c4 = (idx & 7) * 4;
        const float4 v = *(const float4*)(qbase + (size_t)r * EE + c4);
        *(float4*)&qs[r][c4] = v;
    }

    float l_i[4] = {0.f, 0.f, 0.f, 0.f};
    float o[4][4];
#pragma unroll
    for (int i = 0; i < 4; i++)
#pragma unroll
        for (int j = 0; j < 4; j++) o[i][j] = 0.f;

    for (int s0 = s_begin; s0 < s_begin + SCHUNK; s0 += 64) {
        // issue K/V + mask loads early (hide DRAM/L2 latency behind prior sync)
        float4 kv[2], vv[2];
#pragma unroll
        for (int u = 0; u < 2; u++) {
            const int idx = tid + u * 256;
            const int r  = idx >> 3;
            const int c4 = (idx & 7) * 4;
            kv[u] = *(const float4*)(kbase + (size_t)(s0 + r) * EE + c4);
            vv[u] = *(const float4*)(vbase + (size_t)(s0 + r) * EE + c4);
        }
        float mreg[4][4];
#pragma unroll
        for (int i = 0; i < 4; i++) {
            const float* mrow = mbase + (size_t)(y + 16 * i) * SS + s0 + x;
#pragma unroll
            for (int j = 0; j < 4; j++) mreg[i][j] = mrow[16 * j];
        }

        __syncthreads();   // prior iteration's PV readers done with ks/vs
#pragma unroll
        for (int u = 0; u < 2; u++) {
            const int idx = tid + u * 256;
            const int r  = idx >> 3;
            const int c4 = (idx & 7) * 4;
            *(float4*)&ks[r][c4] = kv[u];
            *(float4*)&vs[r][c4] = vv[u];
        }
        __syncthreads();

        // scores: 4q x 4s micro-tile, q rows y+16i, s cols x+16j
        float acc[4][4];
#pragma unroll
        for (int i = 0; i < 4; i++)
#pragma unroll
            for (int j = 0; j < 4; j++) acc[i][j] = 0.f;

#pragma unroll
        for (int d = 0; d < 32; d += 4) {
            float4 a[4], bb[4];
#pragma unroll
            for (int i = 0; i < 4; i++) a[i]  = *(const float4*)&qs[y + 16 * i][d];
#pragma unroll
            for (int j = 0; j < 4; j++) bb[j] = *(const float4*)&ks[x + 16 * j][d];
#pragma unroll
            for (int i = 0; i < 4; i++)
#pragma unroll
                for (int j = 0; j < 4; j++) {
                    acc[i][j] = fmaf(a[i].x, bb[j].x, acc[i][j]);
                    acc[i][j] = fmaf(a[i].y, bb[j].y, acc[i][j]);
                    acc[i][j] = fmaf(a[i].z, bb[j].z, acc[i][j]);
                    acc[i][j] = fmaf(a[i].w, bb[j].w, acc[i][j]);
                }
        }

        // p = exp(score - sfh); no running max, no shuffles, no rescale
#pragma unroll
        for (int i = 0; i < 4; i++) {
#pragma unroll
            for (int j = 0; j < 4; j++) {
                const float p = __expf(fmaf(mreg[i][j], sfh, acc[i][j]) - sfh);
                ps[y + 16 * i][x + 16 * j] = p;
                l_i[i] += p;
            }
        }
        __syncthreads();   // ps fully written

        // PV: o[qg+16i][4xd..] += sum over this thread's 32-key half
#pragma unroll
        for (int s = 0; s < 32; s += 4) {
            const int sb = sh * 32 + s;
            float4 p4[4], v4[4];
#pragma unroll
            for (int i = 0; i < 4; i++) p4[i] = *(const float4*)&ps[qg + 16 * i][sb];
#pragma unroll
            for (int u = 0; u < 4; u++) v4[u] = *(const float4*)&vs[sb + u][xd * 4];
#pragma unroll
            for (int i = 0; i < 4; i++) {
                const float pu[4] = {p4[i].x, p4[i].y, p4[i].z, p4[i].w};
#pragma unroll
                for (int u = 0; u < 4; u++) {
                    o[i][0] = fmaf(pu[u], v4[u].x, o[i][0]);
                    o[i][1] = fmaf(pu[u], v4[u].y, o[i][1]);
                    o[i][2] = fmaf(pu[u], v4[u].z, o[i][2]);
                    o[i][3] = fmaf(pu[u], v4[u].w, o[i][3]);
                }
            }
        }
        // next iteration's first __syncthreads orders ps/vs reuse
    }

    const int pid = (((b * NTQ + tq) * HH + h) * SPLITS + split);

    // reduce l over the 16 x-lanes (once, at the end)
#pragma unroll
    for (int i = 0; i < 4; i++) {
        float L = l_i[i];
        L += __shfl_xor_sync(0xFFFFFFFFu, L, 1);
        L += __shfl_xor_sync(0xFFFFFFFFu, L, 2);
        L += __shfl_xor_sync(0xFFFFFFFFu, L, 4);
        L += __shfl_xor_sync(0xFFFFFFFFu, L, 8);
        if (x == 0) g_pl[pid * 64 + y + 16 * i] = L;
    }

    // combine the two s-halves of o via smem, write unnormalized partial O
    __syncthreads();   // last PV reads of ps done
    if (sh == 1) {
#pragma unroll
        for (int i = 0; i < 4; i++) {
            float4 r; r.x = o[i][0]; r.y = o[i][1]; r.z = o[i][2]; r.w = o[i][3];
            *(float4*)&ps[qg + 16 * i][xd * 4] = r;
        }
    }
    __syncthreads();
    if (sh == 0) {
        float* pob = g_po + (size_t)pid * (64 * 32);
#pragma unroll
        for (int i = 0; i < 4; i++) {
            const float4 t = *(const float4*)&ps[qg + 16 * i][xd * 4];
            float4 r;
            r.x = o[i][0] + t.x; r.y = o[i][1] + t.y;
            r.z = o[i][2] + t.z; r.w = o[i][3] + t.w;
            *(float4*)&pob[(qg + 16 * i) * 32 + xd * 4] = r;
        }
    }
}

// ---------------------------------------------------------------------------
// Combine: all splits share the same implicit max (sf[h]) -> plain sums.
// Grid = 128 blocks (one per (b,tq,h)), 256 threads.
// ---------------------------------------------------------------------------
__global__ __launch_bounds__(256)
void flash_combine_kernel(float* __restrict__ outp)
{
    const int g = blockIdx.x;                 // ((b*NTQ + tq)*HH + h)
    const int h  = g & 7;
    const int tq = (g >> 3) & 3;
    const int b  = g >> 5;
    const int base = g * SPLITS;

    const int tid = threadIdx.x;
    const int row = tid >> 2;                 // 0..63
    const int d0  = (tid & 3) * 8;            // 0,8,16,24

    float L = 0.f;
#pragma unroll
    for (int s = 0; s < SPLITS; s++)
        L += g_pl[(base + s) * 64 + row];
    const float inv = 1.f / L;

    float acc[8];
#pragma unroll
    for (int j = 0; j < 8; j++) acc[j] = 0.f;
#pragma unroll
    for (int s = 0; s < SPLITS; s++) {
        const float* p = g_po + (size_t)(base + s) * (64 * 32) + row * 32 + d0;
        const float4 a = *(const float4*)(p);
        const float4 c = *(const float4*)(p + 4);
        acc[0] += a.x; acc[1] += a.y; acc[2] += a.z; acc[3] += a.w;
        acc[4] += c.x; acc[5] += c.y; acc[6] += c.z; acc[7] += c.w;
    }

    float* ob = outp + ((size_t)b * TT + tq * 64 + row) * EE + h * DD + d0;
    float4 r0, r1;
    r0.x = acc[0] * inv; r0.y = acc[1] * inv; r0.z = acc[2] * inv; r0.w = acc[3] * inv;
    r1.x = acc[4] * inv; r1.y = acc[5] * inv; r1.z = acc[6] * inv; r1.w = acc[7] * inv;
    *(float4*)ob       = r0;
    *(float4*)(ob + 4) = r1;
}

// ---------------------------------------------------------------------------
// Launch: Q/K/V projections -> split-KV flash -> combine -> output projection.
// 6 kernel launches, no sync / alloc / memcpy -> graph-capturable.
// ---------------------------------------------------------------------------
extern "C" void kernel_launch(void* const* d_in, const int* in_sizes, int n_in,
                              void* d_out, int out_size)
{
    (void)in_sizes; (void)n_in; (void)out_size;

    const float* query = (const float*)d_in[0];
    const float* key   = (const float*)d_in[1];
    const float* value = (const float*)d_in[2];
    const float* mask  = (const float*)d_in[3];
    const float* Wq    = (const float*)d_in[4];
    const float* bq    = (const float*)d_in[5];
    const float* Wk    = (const float*)d_in[6];
    const float* bk    = (const float*)d_in[7];
    const float* Wv    = (const float*)d_in[8];
    const float* bv    = (const float*)d_in[9];
    const float* Wo    = (const float*)d_in[10];
    const float* bo    = (const float*)d_in[11];
    const float* sf    = (const float*)d_in[12];
    float* out = (float*)d_out;

    float *qp = nullptr, *kp = nullptr, *vp = nullptr, *att = nullptr;
    cudaGetSymbolAddress((void**)&qp,  g_qp);
    cudaGetSymbolAddress((void**)&kp,  g_kp);
    cudaGetSymbolAddress((void**)&vp,  g_vp);
    cudaGetSymbolAddress((void**)&att, g_att);

    const float qscale = 0.17677669529663687f;  // 1/sqrt(D), folded into Q proj
    const dim3 blk(256);

    gemm64_kernel<<<dim3(4, (BB * TT) / 64), blk>>>(query, Wq, bq, qp, qscale);
    gemm_proj_kernel<<<dim3(2, (BB * SS) / 128), blk>>>(key,   Wk, bk, kp, BB * SS, 1.0f);
    gemm_proj_kernel<<<dim3(2, (BB * SS) / 128), blk>>>(value, Wv, bv, vp, BB * SS, 1.0f);

    flash_attn_kernel<<<dim3(HH * SPLITS, NTQ, BB), blk>>>(qp, kp, vp, mask, sf);
    flash_combine_kernel<<<dim3(BB * NTQ * HH), blk>>>(att);

    gemm64_kernel<<<dim3(4, (BB * TT) / 64), blk>>>(att, Wo, bo, out, 1.0f);
}

// round 11
// speedup vs baseline: 2.1525x; 1.3759x over previous
#include <cuda_runtime.h>
#include <cuda_bf16.h>
#include <math.h>
#include <stdint.h>

// Problem constants (fixed by the reference)
#define BB 4
#define TT 256
#define SS 16384
#define EE 256
#define HH 8
#define DD 32

#define SPLITS 16
#define SCHUNK (SS / SPLITS)          // 1024 keys per block
#define NTQ (TT / 64)                 // 4 query tiles
#define NPID (BB * NTQ * HH * SPLITS) // 2048 partials

// Scratch (allocation-free rule: __device__ globals)
__device__ float g_qp[BB * TT * EE];
__device__ float g_kp[BB * SS * EE];
__device__ float g_vp[BB * SS * EE];
__device__ float g_att[BB * TT * EE];
__device__ float g_po[NPID * 64 * 32];
__device__ float g_pl[NPID * 64];

// ===========================================================================
// mma.sync bf16 (sm_80+ baseline feature; lowers to HMMA on sm_100)
// D[16x8] += A[16x16] @ B[16x8], row.col, f32 accumulate
// ===========================================================================
static __device__ __forceinline__ void mma_bf16(float* d, const uint32_t* a,
                                                const uint32_t* b) {
    asm volatile(
        "mma.sync.aligned.m16n8k16.row.col.f32.bf16.bf16.f32 "
        "{%0,%1,%2,%3}, {%4,%5,%6,%7}, {%8,%9}, {%0,%1,%2,%3};"
        : "+f"(d[0]), "+f"(d[1]), "+f"(d[2]), "+f"(d[3])
        : "r"(a[0]), "r"(a[1]), "r"(a[2]), "r"(a[3]), "r"(b[0]), "r"(b[1]));
}

// Pack two floats' bf16-hi parts / bf16-lo residuals into .b32 words
static __device__ __forceinline__ uint32_t pack_hi(float x, float y) {
    __nv_bfloat162 h = __halves2bfloat162(__float2bfloat16(x), __float2bfloat16(y));
    return *(uint32_t*)&h;
}
static __device__ __forceinline__ uint32_t pack_lo(float x, float y) {
    float hx = __bfloat162float(__float2bfloat16(x));
    float hy = __bfloat162float(__float2bfloat16(y));
    __nv_bfloat162 l = __halves2bfloat162(__float2bfloat16(x - hx),
                                          __float2bfloat16(y - hy));
    return *(uint32_t*)&l;
}

#define GS 36   // smem row stride in words: 16 hi + 16 lo + 4 pad (GS%32==4)

// ---------------------------------------------------------------------------
// bf16-split tensor-core GEMM: C[M,256] = X[M,256] @ W[256,256]^T + bias.
// x = hi + lo (bf16 each). Three term-passes per K-chunk compute
// Xh·Wh + Xh·Wl + Xl·Wh (dropped Xl·Wl ~ 2^-18 relative).
// 128x128 CTA tile, 8 warps (4M x 2N), warp tile 32x64, m16n8k16 fragments.
// K chunked by 32 floats -> 36KB static smem, 2 CTAs/SM.
// grid = (2, M/128, 2{K,V}).
// ---------------------------------------------------------------------------
__global__ __launch_bounds__(256, 2)
void gemm_mma_kernel(const float* __restrict__ Xk, const float* __restrict__ Wk,
                     const float* __restrict__ bk,
                     const float* __restrict__ Xv, const float* __restrict__ Wv,
                     const float* __restrict__ bv,
                     float* __restrict__ Ck, float* __restrict__ Cv)
{
    __shared__ uint32_t sX[128 * GS];   // per row: words 0..15 hi, 16..31 lo
    __shared__ uint32_t sW[128 * GS];

    const int tid  = threadIdx.x;
    const int wid  = tid >> 5;
    const int lane = tid & 31;
    const int r4 = lane >> 2;        // 0..7
    const int p  = lane & 3;         // 0..3
    const int n0 = blockIdx.x * 128;
    const int m0 = blockIdx.y * 128;
    const float* X    = blockIdx.z ? Xv : Xk;
    const float* W    = blockIdx.z ? Wv : Wk;
    const float* bias = blockIdx.z ? bv : bk;
    float*       C    = blockIdx.z ? Cv : Ck;

    const int mw = (wid & 3) * 32;   // warp M offset in tile
    const int nw = (wid >> 2) * 64;  // warp N offset in tile

    float d[2][8][4];
#pragma unroll
    for (int i = 0; i < 2; i++)
#pragma unroll
        for (int j = 0; j < 8; j++)
#pragma unroll
            for (int q = 0; q < 4; q++) d[i][j][q] = 0.f;

    for (int ch = 0; ch < 8; ch++) {
        const int kc0 = ch * 32;

        // issue global loads (each thread: 4 float4 per matrix)
        float4 xf[4], wf[4];
#pragma unroll
        for (int u = 0; u < 4; u++) {
            const int idx = tid + u * 256;           // 0..1023
            const int r   = idx >> 3;                // 0..127
            const int cq  = (idx & 7) * 4;           // f32 col 0..28
            xf[u] = *(const float4*)(X + (size_t)(m0 + r) * EE + kc0 + cq);
            wf[u] = *(const float4*)(W + (size_t)(n0 + r) * EE + kc0 + cq);
        }
        __syncthreads();             // previous chunk's MMAs done with smem

        // convert to bf16 hi/lo and store
#pragma unroll
        for (int u = 0; u < 4; u++) {
            const int idx = tid + u * 256;
            const int r   = idx >> 3;
            const int cw  = (idx & 7) * 2;           // word col 0..14
            uint32_t* px = &sX[r * GS + cw];
            uint32_t* pw = &sW[r * GS + cw];
            px[0]  = pack_hi(xf[u].x, xf[u].y);  px[1]  = pack_hi(xf[u].z, xf[u].w);
            px[16] = pack_lo(xf[u].x, xf[u].y);  px[17] = pack_lo(xf[u].z, xf[u].w);
            pw[0]  = pack_hi(wf[u].x, wf[u].y);  pw[1]  = pack_hi(wf[u].z, wf[u].w);
            pw[16] = pack_lo(wf[u].x, wf[u].y);  pw[17] = pack_lo(wf[u].z, wf[u].w);
        }
        __syncthreads();

        // three split terms: (A half, B half) = (hi,hi), (hi,lo), (lo,hi)
#pragma unroll
        for (int t = 0; t < 3; t++) {
            const int ao = (t == 2) ? 16 : 0;
            const int bo = (t == 1) ? 16 : 0;
#pragma unroll
            for (int ks = 0; ks < 2; ks++) {
                const int kb = ks * 8 + p;
                uint32_t a[2][4];
#pragma unroll
                for (int mf = 0; mf < 2; mf++) {
                    const uint32_t* ax = &sX[(mw + mf * 16 + r4) * GS + ao + kb];
                    a[mf][0] = ax[0];
                    a[mf][1] = ax[8 * GS];
                    a[mf][2] = ax[4];
                    a[mf][3] = ax[8 * GS + 4];
                }
#pragma unroll
                for (int nf = 0; nf < 8; nf++) {
                    const uint32_t* bx = &sW[(nw + nf * 8 + r4) * GS + bo + kb];
                    uint32_t bfr[2];
                    bfr[0] = bx[0];
                    bfr[1] = bx[4];
                    mma_bf16(d[0][nf], a[0], bfr);
                    mma_bf16(d[1][nf], a[1], bfr);
                }
            }
        }
    }

    // epilogue: c0,c1 -> (row, col..col+1); c2,c3 -> (row+8, ...)
#pragma unroll
    for (int mf = 0; mf < 2; mf++) {
#pragma unroll
        for (int nf = 0; nf < 8; nf++) {
            const int col  = n0 + nw + nf * 8 + 2 * p;
            const float b0 = bias[col], b1 = bias[col + 1];
            const int row0 = m0 + mw + mf * 16 + r4;
            float2 v0, v1;
            v0.x = d[mf][nf][0] + b0; v0.y = d[mf][nf][1] + b1;
            v1.x = d[mf][nf][2] + b0; v1.y = d[mf][nf][3] + b1;
            *(float2*)&C[(size_t)row0 * EE + col]       = v0;
            *(float2*)&C[(size_t)(row0 + 8) * EE + col] = v1;
        }
    }
}

// ---------------------------------------------------------------------------
// Small-M GEMM: 64x64 tile, 4x4 micro, BK=16. For M=1024 projections.
// ---------------------------------------------------------------------------
__global__ __launch_bounds__(256)
void gemm64_kernel(const float* __restrict__ X, const float* __restrict__ W,
                   const float* __restrict__ bias, float* __restrict__ C,
                   float scale)
{
    const int K = EE, N = EE;
    __shared__ float As[16][64];
    __shared__ float Bs[16][64];

    const int tid = threadIdx.x;
    const int tx  = tid & 15;
    const int ty  = tid >> 4;
    const int m0  = blockIdx.y * 64;
    const int n0  = blockIdx.x * 64;

    float acc[4][4];
#pragma unroll
    for (int i = 0; i < 4; i++)
#pragma unroll
        for (int j = 0; j < 4; j++) acc[i][j] = 0.f;

    const int lm = tid >> 2;
    const int lk = (tid & 3) * 4;
    const float* Xp = X + (size_t)(m0 + lm) * K + lk;
    const float* Wp = W + (size_t)(n0 + lm) * K + lk;

    for (int k0 = 0; k0 < K; k0 += 16) {
        const float4 xa = *(const float4*)(Xp + k0);
        const float4 wb = *(const float4*)(Wp + k0);
        __syncthreads();
        As[lk + 0][lm] = xa.x; As[lk + 1][lm] = xa.y;
        As[lk + 2][lm] = xa.z; As[lk + 3][lm] = xa.w;
        Bs[lk + 0][lm] = wb.x; Bs[lk + 1][lm] = wb.y;
        Bs[lk + 2][lm] = wb.z; Bs[lk + 3][lm] = wb.w;
        __syncthreads();
#pragma unroll
        for (int kk = 0; kk < 16; kk++) {
            float4 a = *(const float4*)&As[kk][ty * 4];
            float4 b = *(const float4*)&Bs[kk][tx * 4];
            const float av[4] = {a.x, a.y, a.z, a.w};
            const float bw[4] = {b.x, b.y, b.z, b.w};
#pragma unroll
            for (int i = 0; i < 4; i++)
#pragma unroll
                for (int j = 0; j < 4; j++)
                    acc[i][j] = fmaf(av[i], bw[j], acc[i][j]);
        }
    }

    float bv[4];
#pragma unroll
    for (int j = 0; j < 4; j++) bv[j] = bias[n0 + tx * 4 + j];

#pragma unroll
    for (int i = 0; i < 4; i++) {
        const int row = m0 + ty * 4 + i;
        float4 r;
        r.x = (acc[i][0] + bv[0]) * scale;
        r.y = (acc[i][1] + bv[1]) * scale;
        r.z = (acc[i][2] + bv[2]) * scale;
        r.w = (acc[i][3] + bv[3]) * scale;
        *(float4*)&C[(size_t)row * N + n0 + tx * 4] = r;
    }
}

// ---------------------------------------------------------------------------
// Split-KV flash attention, fp32, static softmax max (m == sf[h]).
// Unchanged from R8 (the 528us passing version).
// ---------------------------------------------------------------------------
__global__ __launch_bounds__(256, 3)
void flash_attn_kernel(const float* __restrict__ qp, const float* __restrict__ kp,
                       const float* __restrict__ vp, const float* __restrict__ mask,
                       const float* __restrict__ sf)
{
    __shared__ float qs[64][36];
    __shared__ float ks[64][36];
    __shared__ float vs[64][32];
    __shared__ float ps[64][68];

    const int h     = blockIdx.x & 7;
    const int split = blockIdx.x >> 3;
    const int tq = blockIdx.y;
    const int b  = blockIdx.z;
    const int t0 = tq * 64;
    const int s_begin = split * SCHUNK;
    const int tid = threadIdx.x;
    const int x  = tid & 15;
    const int y  = tid >> 4;
    const int sh = tid >> 7;
    const int qg = (tid >> 3) & 15;
    const int xd = tid & 7;
    const float sfh = sf[h];

    const float* qbase = qp + ((size_t)b * TT + t0) * EE + h * DD;
    const float* kbase = kp + (size_t)b * SS * EE + h * DD;
    const float* vbase = vp + (size_t)b * SS * EE + h * DD;
    const float* mbase = mask + ((size_t)b * TT + t0) * (size_t)SS;

#pragma unroll
    for (int u = 0; u < 2; u++) {
        const int idx = tid + u * 256;
        const int r  = idx >> 3;
        const int c4 = (idx & 7) * 4;
        const float4 v = *(const float4*)(qbase + (size_t)r * EE + c4);
        *(float4*)&qs[r][c4] = v;
    }

    float l_i[4] = {0.f, 0.f, 0.f, 0.f};
    float o[4][4];
#pragma unroll
    for (int i = 0; i < 4; i++)
#pragma unroll
        for (int j = 0; j < 4; j++) o[i][j] = 0.f;

    for (int s0 = s_begin; s0 < s_begin + SCHUNK; s0 += 64) {
        float4 kv[2], vv[2];
#pragma unroll
        for (int u = 0; u < 2; u++) {
            const int idx = tid + u * 256;
            const int r  = idx >> 3;
            const int c4 = (idx & 7) * 4;
            kv[u] = *(const float4*)(kbase + (size_t)(s0 + r) * EE + c4);
            vv[u] = *(const float4*)(vbase + (size_t)(s0 + r) * EE + c4);
        }
        float mreg[4][4];
#pragma unroll
        for (int i = 0; i < 4; i++) {
            const float* mrow = mbase + (size_t)(y + 16 * i) * SS + s0 + x;
#pragma unroll
            for (int j = 0; j < 4; j++) mreg[i][j] = mrow[16 * j];
        }

        __syncthreads();
#pragma unroll
        for (int u = 0; u < 2; u++) {
            const int idx = tid + u * 256;
            const int r  = idx >> 3;
            const int c4 = (idx & 7) * 4;
            *(float4*)&ks[r][c4] = kv[u];
            *(float4*)&vs[r][c4] = vv[u];
        }
        __syncthreads();

        float acc[4][4];
#pragma unroll
        for (int i = 0; i < 4; i++)
#pragma unroll
            for (int j = 0; j < 4; j++) acc[i][j] = 0.f;

#pragma unroll
        for (int dd = 0; dd < 32; dd += 4) {
            float4 a[4], bb[4];
#pragma unroll
            for (int i = 0; i < 4; i++) a[i]  = *(const float4*)&qs[y + 16 * i][dd];
#pragma unroll
            for (int j = 0; j < 4; j++) bb[j] = *(const float4*)&ks[x + 16 * j][dd];
#pragma unroll
            for (int i = 0; i < 4; i++)
#pragma unroll
                for (int j = 0; j < 4; j++) {
                    acc[i][j] = fmaf(a[i].x, bb[j].x, acc[i][j]);
                    acc[i][j] = fmaf(a[i].y, bb[j].y, acc[i][j]);
                    acc[i][j] = fmaf(a[i].z, bb[j].z, acc[i][j]);
                    acc[i][j] = fmaf(a[i].w, bb[j].w, acc[i][j]);
                }
        }

#pragma unroll
        for (int i = 0; i < 4; i++) {
#pragma unroll
            for (int j = 0; j < 4; j++) {
                const float pv = __expf(fmaf(mreg[i][j], sfh, acc[i][j]) - sfh);
                ps[y + 16 * i][x + 16 * j] = pv;
                l_i[i] += pv;
            }
        }
        __syncthreads();

#pragma unroll
        for (int s = 0; s < 32; s += 4) {
            const int sb = sh * 32 + s;
            float4 p4[4], v4[4];
#pragma unroll
            for (int i = 0; i < 4; i++) p4[i] = *(const float4*)&ps[qg + 16 * i][sb];
#pragma unroll
            for (int u = 0; u < 4; u++) v4[u] = *(const float4*)&vs[sb + u][xd * 4];
#pragma unroll
            for (int i = 0; i < 4; i++) {
                const float pu[4] = {p4[i].x, p4[i].y, p4[i].z, p4[i].w};
#pragma unroll
                for (int u = 0; u < 4; u++) {
                    o[i][0] = fmaf(pu[u], v4[u].x, o[i][0]);
                    o[i][1] = fmaf(pu[u], v4[u].y, o[i][1]);
                    o[i][2] = fmaf(pu[u], v4[u].z, o[i][2]);
                    o[i][3] = fmaf(pu[u], v4[u].w, o[i][3]);
                }
            }
        }
    }

    const int pid = (((b * NTQ + tq) * HH + h) * SPLITS + split);

#pragma unroll
    for (int i = 0; i < 4; i++) {
        float L = l_i[i];
        L += __shfl_xor_sync(0xFFFFFFFFu, L, 1);
        L += __shfl_xor_sync(0xFFFFFFFFu, L, 2);
        L += __shfl_xor_sync(0xFFFFFFFFu, L, 4);
        L += __shfl_xor_sync(0xFFFFFFFFu, L, 8);
        if (x == 0) g_pl[pid * 64 + y + 16 * i] = L;
    }

    __syncthreads();
    if (sh == 1) {
#pragma unroll
        for (int i = 0; i < 4; i++) {
            float4 r; r.x = o[i][0]; r.y = o[i][1]; r.z = o[i][2]; r.w = o[i][3];
            *(float4*)&ps[qg + 16 * i][xd * 4] = r;
        }
    }
    __syncthreads();
    if (sh == 0) {
        float* pob = g_po + (size_t)pid * (64 * 32);
#pragma unroll
        for (int i = 0; i < 4; i++) {
            const float4 t = *(const float4*)&ps[qg + 16 * i][xd * 4];
            float4 r;
            r.x = o[i][0] + t.x; r.y = o[i][1] + t.y;
            r.z = o[i][2] + t.z; r.w = o[i][3] + t.w;
            *(float4*)&pob[(qg + 16 * i) * 32 + xd * 4] = r;
        }
    }
}

// ---------------------------------------------------------------------------
// Combine: all splits share the same implicit max -> plain sums.
// ---------------------------------------------------------------------------
__global__ __launch_bounds__(256)
void flash_combine_kernel(float* __restrict__ outp)
{
    const int g = blockIdx.x;
    const int h  = g & 7;
    const int tq = (g >> 3) & 3;
    const int b  = g >> 5;
    const int base = g * SPLITS;

    const int tid = threadIdx.x;
    const int row = tid >> 2;
    const int d0  = (tid & 3) * 8;

    float L = 0.f;
#pragma unroll
    for (int s = 0; s < SPLITS; s++)
        L += g_pl[(base + s) * 64 + row];
    const float inv = 1.f / L;

    float acc[8];
#pragma unroll
    for (int j = 0; j < 8; j++) acc[j] = 0.f;
#pragma unroll
    for (int s = 0; s < SPLITS; s++) {
        const float* p = g_po + (size_t)(base + s) * (64 * 32) + row * 32 + d0;
        const float4 a = *(const float4*)(p);
        const float4 c = *(const float4*)(p + 4);
        acc[0] += a.x; acc[1] += a.y; acc[2] += a.z; acc[3] += a.w;
        acc[4] += c.x; acc[5] += c.y; acc[6] += c.z; acc[7] += c.w;
    }

    float* ob = outp + ((size_t)b * TT + tq * 64 + row) * EE + h * DD + d0;
    float4 r0, r1;
    r0.x = acc[0] * inv; r0.y = acc[1] * inv; r0.z = acc[2] * inv; r0.w = acc[3] * inv;
    r1.x = acc[4] * inv; r1.y = acc[5] * inv; r1.z = acc[6] * inv; r1.w = acc[7] * inv;
    *(float4*)ob       = r0;
    *(float4*)(ob + 4) = r1;
}

// ---------------------------------------------------------------------------
// Launch. 5 kernel launches, no sync / alloc / memcpy / statics -> capturable.
// ---------------------------------------------------------------------------
extern "C" void kernel_launch(void* const* d_in, const int* in_sizes, int n_in,
                              void* d_out, int out_size)
{
    (void)in_sizes; (void)n_in; (void)out_size;

    const float* query = (const float*)d_in[0];
    const float* key   = (const float*)d_in[1];
    const float* value = (const float*)d_in[2];
    const float* mask  = (const float*)d_in[3];
    const float* Wq    = (const float*)d_in[4];
    const float* bq    = (const float*)d_in[5];
    const float* Wk    = (const float*)d_in[6];
    const float* bk    = (const float*)d_in[7];
    const float* Wv    = (const float*)d_in[8];
    const float* bv    = (const float*)d_in[9];
    const float* Wo    = (const float*)d_in[10];
    const float* bo    = (const float*)d_in[11];
    const float* sf    = (const float*)d_in[12];
    float* out = (float*)d_out;

    float *qp = nullptr, *kp = nullptr, *vp = nullptr, *att = nullptr;
    cudaGetSymbolAddress((void**)&qp,  g_qp);
    cudaGetSymbolAddress((void**)&kp,  g_kp);
    cudaGetSymbolAddress((void**)&vp,  g_vp);
    cudaGetSymbolAddress((void**)&att, g_att);

    const float qscale = 0.17677669529663687f;  // 1/sqrt(D), folded into Q proj
    const dim3 blk(256);

    // K and V projections fused into one tensor-core launch (grid.z selects)
    gemm_mma_kernel<<<dim3(2, (BB * SS) / 128, 2), blk>>>(
        key, Wk, bk, value, Wv, bv, kp, vp);

    gemm64_kernel<<<dim3(4, (BB * TT) / 64), blk>>>(query, Wq, bq, qp, qscale);

    flash_attn_kernel<<<dim3(HH * SPLITS, NTQ, BB), blk>>>(qp, kp, vp, mask, sf);
    flash_combine_kernel<<<dim3(BB * NTQ * HH), blk>>>(att);

    gemm64_kernel<<<dim3(4, (BB * TT) / 64), blk>>>(att, Wo, bo, out, 1.0f);
}

// round 12
// speedup vs baseline: 3.1361x; 1.4570x over previous
#include <cuda_runtime.h>
#include <cuda_bf16.h>
#include <math.h>
#include <stdint.h>

// Problem constants (fixed by the reference)
#define BB 4
#define TT 256
#define SS 16384
#define EE 256
#define HH 8
#define DD 32

#define SPLITS 16
#define SCHUNK (SS / SPLITS)          // 1024 keys per block
#define NTQ (TT / 64)                 // 4 query tiles
#define NPID (BB * NTQ * HH * SPLITS) // 2048 partials

// Scratch (allocation-free rule: __device__ globals)
__device__ float g_qp[BB * TT * EE];
__device__ float g_kp[BB * SS * EE];
__device__ float g_vp[BB * SS * EE];
__device__ float g_att[BB * TT * EE];
__device__ float g_po[NPID * 64 * 32];
__device__ float g_pl[NPID * 64];

// ===========================================================================
// mma.sync bf16 (sm_80+ baseline; lowers to HMMA on sm_100)
// D[16x8] += A[16x16] @ B[16x8], row.col, f32 accumulate
// ===========================================================================
static __device__ __forceinline__ void mma_bf16(float* d, const uint32_t* a,
                                                const uint32_t* b) {
    asm volatile(
        "mma.sync.aligned.m16n8k16.row.col.f32.bf16.bf16.f32 "
        "{%0,%1,%2,%3}, {%4,%5,%6,%7}, {%8,%9}, {%0,%1,%2,%3};"
        : "+f"(d[0]), "+f"(d[1]), "+f"(d[2]), "+f"(d[3])
        : "r"(a[0]), "r"(a[1]), "r"(a[2]), "r"(a[3]), "r"(b[0]), "r"(b[1]));
}

static __device__ __forceinline__ uint32_t pack_hi(float x, float y) {
    __nv_bfloat162 h = __halves2bfloat162(__float2bfloat16(x), __float2bfloat16(y));
    return *(uint32_t*)&h;
}
static __device__ __forceinline__ uint32_t pack_lo(float x, float y) {
    float hx = __bfloat162float(__float2bfloat16(x));
    float hy = __bfloat162float(__float2bfloat16(y));
    __nv_bfloat162 l = __halves2bfloat162(__float2bfloat16(x - hx),
                                          __float2bfloat16(y - hy));
    return *(uint32_t*)&l;
}

#define GS 36   // smem row stride in words: 16 hi + 16 lo + 4 pad

// ---------------------------------------------------------------------------
// bf16-split tensor-core GEMM (unchanged from R11 passing version).
// ---------------------------------------------------------------------------
__global__ __launch_bounds__(256, 2)
void gemm_mma_kernel(const float* __restrict__ Xk, const float* __restrict__ Wk,
                     const float* __restrict__ bk,
                     const float* __restrict__ Xv, const float* __restrict__ Wv,
                     const float* __restrict__ bv,
                     float* __restrict__ Ck, float* __restrict__ Cv)
{
    __shared__ uint32_t sX[128 * GS];
    __shared__ uint32_t sW[128 * GS];

    const int tid  = threadIdx.x;
    const int wid  = tid >> 5;
    const int lane = tid & 31;
    const int r4 = lane >> 2;
    const int p  = lane & 3;
    const int n0 = blockIdx.x * 128;
    const int m0 = blockIdx.y * 128;
    const float* X    = blockIdx.z ? Xv : Xk;
    const float* W    = blockIdx.z ? Wv : Wk;
    const float* bias = blockIdx.z ? bv : bk;
    float*       C    = blockIdx.z ? Cv : Ck;

    const int mw = (wid & 3) * 32;
    const int nw = (wid >> 2) * 64;

    float d[2][8][4];
#pragma unroll
    for (int i = 0; i < 2; i++)
#pragma unroll
        for (int j = 0; j < 8; j++)
#pragma unroll
            for (int q = 0; q < 4; q++) d[i][j][q] = 0.f;

    for (int ch = 0; ch < 8; ch++) {
        const int kc0 = ch * 32;
        float4 xf[4], wf[4];
#pragma unroll
        for (int u = 0; u < 4; u++) {
            const int idx = tid + u * 256;
            const int r   = idx >> 3;
            const int cq  = (idx & 7) * 4;
            xf[u] = *(const float4*)(X + (size_t)(m0 + r) * EE + kc0 + cq);
            wf[u] = *(const float4*)(W + (size_t)(n0 + r) * EE + kc0 + cq);
        }
        __syncthreads();
#pragma unroll
        for (int u = 0; u < 4; u++) {
            const int idx = tid + u * 256;
            const int r   = idx >> 3;
            const int cw  = (idx & 7) * 2;
            uint32_t* px = &sX[r * GS + cw];
            uint32_t* pw = &sW[r * GS + cw];
            px[0]  = pack_hi(xf[u].x, xf[u].y);  px[1]  = pack_hi(xf[u].z, xf[u].w);
            px[16] = pack_lo(xf[u].x, xf[u].y);  px[17] = pack_lo(xf[u].z, xf[u].w);
            pw[0]  = pack_hi(wf[u].x, wf[u].y);  pw[1]  = pack_hi(wf[u].z, wf[u].w);
            pw[16] = pack_lo(wf[u].x, wf[u].y);  pw[17] = pack_lo(wf[u].z, wf[u].w);
        }
        __syncthreads();

#pragma unroll
        for (int t = 0; t < 3; t++) {
            const int ao = (t == 2) ? 16 : 0;
            const int bo = (t == 1) ? 16 : 0;
#pragma unroll
            for (int ks = 0; ks < 2; ks++) {
                const int kb = ks * 8 + p;
                uint32_t a[2][4];
#pragma unroll
                for (int mf = 0; mf < 2; mf++) {
                    const uint32_t* ax = &sX[(mw + mf * 16 + r4) * GS + ao + kb];
                    a[mf][0] = ax[0];
                    a[mf][1] = ax[8 * GS];
                    a[mf][2] = ax[4];
                    a[mf][3] = ax[8 * GS + 4];
                }
#pragma unroll
                for (int nf = 0; nf < 8; nf++) {
                    const uint32_t* bx = &sW[(nw + nf * 8 + r4) * GS + bo + kb];
                    uint32_t bfr[2];
                    bfr[0] = bx[0];
                    bfr[1] = bx[4];
                    mma_bf16(d[0][nf], a[0], bfr);
                    mma_bf16(d[1][nf], a[1], bfr);
                }
            }
        }
    }

#pragma unroll
    for (int mf = 0; mf < 2; mf++) {
#pragma unroll
        for (int nf = 0; nf < 8; nf++) {
            const int col  = n0 + nw + nf * 8 + 2 * p;
            const float b0 = bias[col], b1 = bias[col + 1];
            const int row0 = m0 + mw + mf * 16 + r4;
            float2 v0, v1;
            v0.x = d[mf][nf][0] + b0; v0.y = d[mf][nf][1] + b1;
            v1.x = d[mf][nf][2] + b0; v1.y = d[mf][nf][3] + b1;
            *(float2*)&C[(size_t)row0 * EE + col]       = v0;
            *(float2*)&C[(size_t)(row0 + 8) * EE + col] = v1;
        }
    }
}

// ---------------------------------------------------------------------------
// Small-M GEMM: 64x64 tile, 4x4 micro, BK=16. For M=1024 projections.
// ---------------------------------------------------------------------------
__global__ __launch_bounds__(256)
void gemm64_kernel(const float* __restrict__ X, const float* __restrict__ W,
                   const float* __restrict__ bias, float* __restrict__ C,
                   float scale)
{
    const int K = EE, N = EE;
    __shared__ float As[16][64];
    __shared__ float Bs[16][64];

    const int tid = threadIdx.x;
    const int tx  = tid & 15;
    const int ty  = tid >> 4;
    const int m0  = blockIdx.y * 64;
    const int n0  = blockIdx.x * 64;

    float acc[4][4];
#pragma unroll
    for (int i = 0; i < 4; i++)
#pragma unroll
        for (int j = 0; j < 4; j++) acc[i][j] = 0.f;

    const int lm = tid >> 2;
    const int lk = (tid & 3) * 4;
    const float* Xp = X + (size_t)(m0 + lm) * K + lk;
    const float* Wp = W + (size_t)(n0 + lm) * K + lk;

    for (int k0 = 0; k0 < K; k0 += 16) {
        const float4 xa = *(const float4*)(Xp + k0);
        const float4 wb = *(const float4*)(Wp + k0);
        __syncthreads();
        As[lk + 0][lm] = xa.x; As[lk + 1][lm] = xa.y;
        As[lk + 2][lm] = xa.z; As[lk + 3][lm] = xa.w;
        Bs[lk + 0][lm] = wb.x; Bs[lk + 1][lm] = wb.y;
        Bs[lk + 2][lm] = wb.z; Bs[lk + 3][lm] = wb.w;
        __syncthreads();
#pragma unroll
        for (int kk = 0; kk < 16; kk++) {
            float4 a = *(const float4*)&As[kk][ty * 4];
            float4 b = *(const float4*)&Bs[kk][tx * 4];
            const float av[4] = {a.x, a.y, a.z, a.w};
            const float bw[4] = {b.x, b.y, b.z, b.w};
#pragma unroll
            for (int i = 0; i < 4; i++)
#pragma unroll
                for (int j = 0; j < 4; j++)
                    acc[i][j] = fmaf(av[i], bw[j], acc[i][j]);
        }
    }

    float bv[4];
#pragma unroll
    for (int j = 0; j < 4; j++) bv[j] = bias[n0 + tx * 4 + j];

#pragma unroll
    for (int i = 0; i < 4; i++) {
        const int row = m0 + ty * 4 + i;
        float4 r;
        r.x = (acc[i][0] + bv[0]) * scale;
        r.y = (acc[i][1] + bv[1]) * scale;
        r.z = (acc[i][2] + bv[2]) * scale;
        r.w = (acc[i][3] + bv[3]) * scale;
        *(float4*)&C[(size_t)row * N + n0 + tx * 4] = r;
    }
}

// ---------------------------------------------------------------------------
// Tensor-core split-KV flash attention. bf16 hi/lo split on Q,K,P,V
// (3 MMA terms each for QK and PV; dropped lo·lo ~2^-18). Static softmax
// max (m == sf[h]) as validated in R8-R11.
// Block = (b, h, 64-q tile, split); 256 threads, 8 warps:
//   warp w: mw=(w&3)*16 (q rows), nwi=w>>2 (which 32-key half / s-range).
// Score tile 64x64 per chunk; each warp: 1 m16 x 4 n8 C-frags.
// P stays in registers (C-frag of two adjacent n8 tiles == A-frag of k16).
// V packed bf16x2 along s, row stride 40 words -> conflict-free B-frags.
// ---------------------------------------------------------------------------
__global__ __launch_bounds__(256, 2)
void flash_mma_kernel(const float* __restrict__ qp, const float* __restrict__ kp,
                      const float* __restrict__ vp, const float* __restrict__ mask,
                      const float* __restrict__ sf)
{
    __shared__ uint32_t sQ[64 * GS];     // q rows, 16 hi + 16 lo words
    __shared__ uint32_t sK[64 * GS];     // s rows, same layout
    __shared__ uint32_t sVh[32 * 40];    // word(s2,d) = bf16x2(V[2s2][d],V[2s2+1][d])
    __shared__ uint32_t sVl[32 * 40];
    __shared__ float    sL[2][64];
    __shared__ float    sO[64][33];

    const int h     = blockIdx.x & 7;
    const int split = blockIdx.x >> 3;
    const int tq = blockIdx.y;
    const int b  = blockIdx.z;
    const int t0 = tq * 64;
    const int s_begin = split * SCHUNK;

    const int tid  = threadIdx.x;
    const int wid  = tid >> 5;
    const int lane = tid & 31;
    const int r4 = lane >> 2;
    const int p  = lane & 3;
    const int mw  = (wid & 3) * 16;      // q-row base of this warp
    const int nwi = wid >> 2;            // 0/1: s half
    const int nw  = nwi * 32;            // s base within chunk
    const float sfh = sf[h];

    const float* qbase = qp + ((size_t)b * TT + t0) * EE + h * DD;
    const float* kbase = kp + (size_t)b * SS * EE + h * DD;
    const float* vbase = vp + (size_t)b * SS * EE + h * DD;
    const float* mbase = mask + ((size_t)b * TT + t0) * (size_t)SS;

    // load + convert Q tile (64 x 32) once
#pragma unroll
    for (int u = 0; u < 2; u++) {
        const int idx = tid + u * 256;
        const int r   = idx >> 3;
        const int cq  = (idx & 7) * 4;
        const float4 f = *(const float4*)(qbase + (size_t)r * EE + cq);
        const int cw = (idx & 7) * 2;
        uint32_t* px = &sQ[r * GS + cw];
        px[0]  = pack_hi(f.x, f.y);  px[1]  = pack_hi(f.z, f.w);
        px[16] = pack_lo(f.x, f.y);  px[17] = pack_lo(f.z, f.w);
    }

    const int vs2 = tid >> 3;            // 0..31 (s-pair index for V staging)
    const int vd4 = (tid & 7) * 4;       // 0..28 (d group)

    float o[4][4];
#pragma unroll
    for (int i = 0; i < 4; i++)
#pragma unroll
        for (int j = 0; j < 4; j++) o[i][j] = 0.f;
    float l2[2] = {0.f, 0.f};

    for (int s0 = s_begin; s0 < s_begin + SCHUNK; s0 += 64) {
        // stage K, V, mask loads in registers (hide latency behind the sync)
        float4 kf[2];
#pragma unroll
        for (int u = 0; u < 2; u++) {
            const int idx = tid + u * 256;
            const int r   = idx >> 3;
            const int cq  = (idx & 7) * 4;
            kf[u] = *(const float4*)(kbase + (size_t)(s0 + r) * EE + cq);
        }
        const float4 va = *(const float4*)(vbase + (size_t)(s0 + 2 * vs2) * EE + vd4);
        const float4 vb = *(const float4*)(vbase + (size_t)(s0 + 2 * vs2 + 1) * EE + vd4);
        float2 mk[4][2];
#pragma unroll
        for (int nf = 0; nf < 4; nf++) {
            const int col = s0 + nw + nf * 8 + 2 * p;
            const size_t rowoff = (size_t)(mw + r4) * SS;
            mk[nf][0] = *(const float2*)(mbase + rowoff + col);
            mk[nf][1] = *(const float2*)(mbase + rowoff + 8 * SS + col);
        }

        __syncthreads();   // previous chunk's fragment LDS done (also orders sQ)

        // store K (hi/lo) and V (paired bf16x2 along s)
#pragma unroll
        for (int u = 0; u < 2; u++) {
            const int idx = tid + u * 256;
            const int r   = idx >> 3;
            const int cw  = (idx & 7) * 2;
            uint32_t* pk = &sK[r * GS + cw];
            pk[0]  = pack_hi(kf[u].x, kf[u].y);  pk[1]  = pack_hi(kf[u].z, kf[u].w);
            pk[16] = pack_lo(kf[u].x, kf[u].y);  pk[17] = pack_lo(kf[u].z, kf[u].w);
        }
        {
            uint32_t* ph = &sVh[vs2 * 40 + vd4];
            uint32_t* pl = &sVl[vs2 * 40 + vd4];
            ph[0] = pack_hi(va.x, vb.x); ph[1] = pack_hi(va.y, vb.y);
            ph[2] = pack_hi(va.z, vb.z); ph[3] = pack_hi(va.w, vb.w);
            pl[0] = pack_lo(va.x, vb.x); pl[1] = pack_lo(va.y, vb.y);
            pl[2] = pack_lo(va.z, vb.z); pl[3] = pack_lo(va.w, vb.w);
        }
        __syncthreads();

        // ---- QK^T: c[nf][4] = scores for rows (mw+r4, +8) x cols (nw+nf*8+2p, +1)
        float c[4][4];
#pragma unroll
        for (int nf = 0; nf < 4; nf++)
#pragma unroll
            for (int q = 0; q < 4; q++) c[nf][q] = 0.f;

#pragma unroll
        for (int ks = 0; ks < 2; ks++) {
            const int kb = ks * 8 + p;
            const uint32_t* ax = &sQ[(mw + r4) * GS + kb];
            uint32_t ah[4], al[4];
            ah[0] = ax[0];      ah[1] = ax[8 * GS];      ah[2] = ax[4];      ah[3] = ax[8 * GS + 4];
            al[0] = ax[16];     al[1] = ax[8 * GS + 16]; al[2] = ax[20];     al[3] = ax[8 * GS + 20];
#pragma unroll
            for (int nf = 0; nf < 4; nf++) {
                const uint32_t* bx = &sK[(nw + nf * 8 + r4) * GS + kb];
                uint32_t bh[2], bl[2];
                bh[0] = bx[0];  bh[1] = bx[4];
                bl[0] = bx[16]; bl[1] = bx[20];
                mma_bf16(c[nf], ah, bh);
                mma_bf16(c[nf], ah, bl);
                mma_bf16(c[nf], al, bh);
            }
        }

        // ---- bias + exp (static max sfh) + l accumulation; P overwrites c
#pragma unroll
        for (int nf = 0; nf < 4; nf++) {
            c[nf][0] = __expf(fmaf(mk[nf][0].x, sfh, c[nf][0]) - sfh);
            c[nf][1] = __expf(fmaf(mk[nf][0].y, sfh, c[nf][1]) - sfh);
            c[nf][2] = __expf(fmaf(mk[nf][1].x, sfh, c[nf][2]) - sfh);
            c[nf][3] = __expf(fmaf(mk[nf][1].y, sfh, c[nf][3]) - sfh);
            l2[0] += c[nf][0] + c[nf][1];
            l2[1] += c[nf][2] + c[nf][3];
        }

        // ---- PV: o[nfd][4] += P[rows, warp's 32 s] @ V[warp's 32 s, d]
#pragma unroll
        for (int ks = 0; ks < 2; ks++) {
            uint32_t ah[4], al[4];
            ah[0] = pack_hi(c[2 * ks][0],     c[2 * ks][1]);
            ah[1] = pack_hi(c[2 * ks][2],     c[2 * ks][3]);
            ah[2] = pack_hi(c[2 * ks + 1][0], c[2 * ks + 1][1]);
            ah[3] = pack_hi(c[2 * ks + 1][2], c[2 * ks + 1][3]);
            al[0] = pack_lo(c[2 * ks][0],     c[2 * ks][1]);
            al[1] = pack_lo(c[2 * ks][2],     c[2 * ks][3]);
            al[2] = pack_lo(c[2 * ks + 1][0], c[2 * ks + 1][1]);
            al[3] = pack_lo(c[2 * ks + 1][2], c[2 * ks + 1][3]);
            const int s2b = nw / 2 + ks * 8 + p;   // s-pair row in sV
#pragma unroll
            for (int nfd = 0; nfd < 4; nfd++) {
                const uint32_t* bxh = &sVh[s2b * 40 + nfd * 8 + r4];
                const uint32_t* bxl = &sVl[s2b * 40 + nfd * 8 + r4];
                uint32_t vh[2], vl[2];
                vh[0] = bxh[0]; vh[1] = bxh[4 * 40];
                vl[0] = bxl[0]; vl[1] = bxl[4 * 40];
                mma_bf16(o[nfd], ah, vh);
                mma_bf16(o[nfd], ah, vl);
                mma_bf16(o[nfd], al, vh);
            }
        }
    }

    // ---- epilogue: reduce l, combine the two s-half partials of o, write
    l2[0] += __shfl_xor_sync(0xFFFFFFFFu, l2[0], 1);
    l2[0] += __shfl_xor_sync(0xFFFFFFFFu, l2[0], 2);
    l2[1] += __shfl_xor_sync(0xFFFFFFFFu, l2[1], 1);
    l2[1] += __shfl_xor_sync(0xFFFFFFFFu, l2[1], 2);
    if (p == 0) {
        sL[nwi][mw + r4]     = l2[0];
        sL[nwi][mw + 8 + r4] = l2[1];
    }
    __syncthreads();   // sL ready; last chunk's LDS done

    const int pid = (((b * NTQ + tq) * HH + h) * SPLITS + split);
    if (tid < 64)
        g_pl[pid * 64 + tid] = sL[0][tid] + sL[1][tid];

    if (nwi == 1) {
#pragma unroll
        for (int nfd = 0; nfd < 4; nfd++) {
            const int col = nfd * 8 + 2 * p;
            sO[mw + r4][col]     = o[nfd][0];
            sO[mw + r4][col + 1] = o[nfd][1];
            sO[mw + 8 + r4][col]     = o[nfd][2];
            sO[mw + 8 + r4][col + 1] = o[nfd][3];
        }
    }
    __syncthreads();
    if (nwi == 0) {
        float* pob = g_po + (size_t)pid * (64 * 32);
#pragma unroll
        for (int nfd = 0; nfd < 4; nfd++) {
            const int col = nfd * 8 + 2 * p;
            float2 r0, r1;
            r0.x = o[nfd][0] + sO[mw + r4][col];
            r0.y = o[nfd][1] + sO[mw + r4][col + 1];
            r1.x = o[nfd][2] + sO[mw + 8 + r4][col];
            r1.y = o[nfd][3] + sO[mw + 8 + r4][col + 1];
            *(float2*)&pob[(mw + r4) * 32 + col]     = r0;
            *(float2*)&pob[(mw + 8 + r4) * 32 + col] = r1;
        }
    }
}

// ---------------------------------------------------------------------------
// Combine: all splits share the same implicit max -> plain sums.
// ---------------------------------------------------------------------------
__global__ __launch_bounds__(256)
void flash_combine_kernel(float* __restrict__ outp)
{
    const int g = blockIdx.x;
    const int h  = g & 7;
    const int tq = (g >> 3) & 3;
    const int b  = g >> 5;
    const int base = g * SPLITS;

    const int tid = threadIdx.x;
    const int row = tid >> 2;
    const int d0  = (tid & 3) * 8;

    float L = 0.f;
#pragma unroll
    for (int s = 0; s < SPLITS; s++)
        L += g_pl[(base + s) * 64 + row];
    const float inv = 1.f / L;

    float acc[8];
#pragma unroll
    for (int j = 0; j < 8; j++) acc[j] = 0.f;
#pragma unroll
    for (int s = 0; s < SPLITS; s++) {
        const float* p = g_po + (size_t)(base + s) * (64 * 32) + row * 32 + d0;
        const float4 a = *(const float4*)(p);
        const float4 c = *(const float4*)(p + 4);
        acc[0] += a.x; acc[1] += a.y; acc[2] += a.z; acc[3] += a.w;
        acc[4] += c.x; acc[5] += c.y; acc[6] += c.z; acc[7] += c.w;
    }

    float* ob = outp + ((size_t)b * TT + tq * 64 + row) * EE + h * DD + d0;
    float4 r0, r1;
    r0.x = acc[0] * inv; r0.y = acc[1] * inv; r0.z = acc[2] * inv; r0.w = acc[3] * inv;
    r1.x = acc[4] * inv; r1.y = acc[5] * inv; r1.z = acc[6] * inv; r1.w = acc[7] * inv;
    *(float4*)ob       = r0;
    *(float4*)(ob + 4) = r1;
}

// ---------------------------------------------------------------------------
// Launch. 5 kernel launches, no sync / alloc / memcpy / statics -> capturable.
// ---------------------------------------------------------------------------
extern "C" void kernel_launch(void* const* d_in, const int* in_sizes, int n_in,
                              void* d_out, int out_size)
{
    (void)in_sizes; (void)n_in; (void)out_size;

    const float* query = (const float*)d_in[0];
    const float* key   = (const float*)d_in[1];
    const float* value = (const float*)d_in[2];
    const float* mask  = (const float*)d_in[3];
    const float* Wq    = (const float*)d_in[4];
    const float* bq    = (const float*)d_in[5];
    const float* Wk    = (const float*)d_in[6];
    const float* bk    = (const float*)d_in[7];
    const float* Wv    = (const float*)d_in[8];
    const float* bv    = (const float*)d_in[9];
    const float* Wo    = (const float*)d_in[10];
    const float* bo    = (const float*)d_in[11];
    const float* sf    = (const float*)d_in[12];
    float* out = (float*)d_out;

    float *qp = nullptr, *kp = nullptr, *vp = nullptr, *att = nullptr;
    cudaGetSymbolAddress((void**)&qp,  g_qp);
    cudaGetSymbolAddress((void**)&kp,  g_kp);
    cudaGetSymbolAddress((void**)&vp,  g_vp);
    cudaGetSymbolAddress((void**)&att, g_att);

    const float qscale = 0.17677669529663687f;  // 1/sqrt(D), folded into Q proj
    const dim3 blk(256);

    // K and V projections fused into one tensor-core launch (grid.z selects)
    gemm_mma_kernel<<<dim3(2, (BB * SS) / 128, 2), blk>>>(
        key, Wk, bk, value, Wv, bv, kp, vp);

    gemm64_kernel<<<dim3(4, (BB * TT) / 64), blk>>>(query, Wq, bq, qp, qscale);

    flash_mma_kernel<<<dim3(HH * SPLITS, NTQ, BB), blk>>>(qp, kp, vp, mask, sf);
    flash_combine_kernel<<<dim3(BB * NTQ * HH), blk>>>(att);

    gemm64_kernel<<<dim3(4, (BB * TT) / 64), blk>>>(att, Wo, bo, out, 1.0f);
}